// round 13
// baseline (speedup 1.0000x reference)
#include <cuda_runtime.h>
#include <cuda_fp16.h>
#include <cstdint>
#include <cstddef>

// Problem constants
#define H_DIM   2048
#define S_LEN   2048
#define B_SZ    2
#define NHEADS  16
#define NKVH    8
#define HD      128
#define FF_DIM  5632
#define MROWS   (B_SZ * S_LEN)          // 4096
#define QKV_LD  4096                    // q(2048) | k(1024) | v(1024)
#define ATT_SCALE 0.08838834764831845f  // 1/sqrt(128)

// ---------------------------------------------------------------------------
// Scratch (activations fp16; residual stream fp32)
// ---------------------------------------------------------------------------
__device__ __half g_xn  [(size_t)MROWS * H_DIM];
__device__ __half g_qkv [(size_t)MROWS * QKV_LD];
__device__ __half g_attn[(size_t)MROWS * H_DIM];
__device__ float  g_h   [(size_t)MROWS * H_DIM];
__device__ __half g_gate[(size_t)MROWS * FF_DIM];
__device__ __half g_ff  [(size_t)MROWS * FF_DIM];
// fp16 weight copies
__device__ __half g_wqkv[(size_t)4096 * 2048];
__device__ __half g_wo[(size_t)2048 * 2048];
__device__ __half g_wg[(size_t)FF_DIM * 2048];
__device__ __half g_wu[(size_t)FF_DIM * 2048];
__device__ __half g_wd[(size_t)2048 * FF_DIM];

// ---------------------------------------------------------------------------
// Helpers (family-portable PTX: cp.async + mma.sync + ldmatrix)
// ---------------------------------------------------------------------------
__device__ __forceinline__ uint32_t smem_u32(const void* p) {
    uint32_t a;
    asm("{ .reg .u64 t; cvta.to.shared.u64 t, %1; cvt.u32.u64 %0, t; }"
        : "=r"(a) : "l"(p));
    return a;
}

__device__ __forceinline__ void cp_async16(uint32_t dst, const void* src) {
    asm volatile("cp.async.cg.shared.global [%0], [%1], 16;"
                 :: "r"(dst), "l"(src) : "memory");
}
#define CP_COMMIT() asm volatile("cp.async.commit_group;" ::: "memory")
#define CP_WAIT0()  asm volatile("cp.async.wait_group 0;" ::: "memory")
#define CP_WAIT1()  asm volatile("cp.async.wait_group 1;" ::: "memory")

#define LDSM_X4(r0, r1, r2, r3, addr)                                        \
    asm volatile("ldmatrix.sync.aligned.m8n8.x4.shared.b16 {%0,%1,%2,%3}, [%4];" \
        : "=r"(r0), "=r"(r1), "=r"(r2), "=r"(r3) : "r"(addr))

// m16n8k16 fp16 MMA, fp32 accumulate (sm_80+ family-portable)
__device__ __forceinline__ void mma_f16(float* d, const uint32_t* a, const uint32_t* b) {
    asm volatile(
        "mma.sync.aligned.m16n8k16.row.col.f32.f16.f16.f32 "
        "{%0,%1,%2,%3}, {%4,%5,%6,%7}, {%8,%9}, {%0,%1,%2,%3};"
        : "+f"(d[0]), "+f"(d[1]), "+f"(d[2]), "+f"(d[3])
        : "r"(a[0]), "r"(a[1]), "r"(a[2]), "r"(a[3]), "r"(b[0]), "r"(b[1]));
}

__device__ __forceinline__ float silu_f(float x) {
    return x / (1.0f + __expf(-x));
}

// ---------------------------------------------------------------------------
// Weight convert: float -> fp16 (grid-stride, 4 float4 per iteration of ILP)
// ---------------------------------------------------------------------------
__global__ __launch_bounds__(256) void cvt_wh_k(
    const float4* __restrict__ in, __half* __restrict__ out, int n4)
{
    const int stride = gridDim.x * 256;
    for (int i = blockIdx.x * 256 + threadIdx.x; i < n4; i += stride) {
        float4 v = in[i];
        half2* o = (half2*)(out + (size_t)i * 4);
        o[0] = __floats2half2_rn(v.x, v.y);
        o[1] = __floats2half2_rn(v.z, v.w);
    }
}

// ---------------------------------------------------------------------------
// fp16 tensor-core NT GEMM: C[m,n] = sum_k A[m,k]*B[n,k], epilogue modes:
//  0: half  C = h(acc)                   (raw half; used for gate)
//  1: float C = acc + Res(float)
//  2: half  C = h( silu(Res:half) * acc ) (fused SwiGLU; Res = gate fp16)
//  3: half  C = h( acc * (n0<2048 ? ATT_SCALE : 1) )  (fused QKV post)
// BM=BN=128, BK=64 halves, 8 warps (2x4), warp tile 64x32.
// 3-stage cp.async ring (wait_group 1 => two chunks in flight).
// Smem rows padded to 72 halves (144B = 9x16B, conflict-free ldmatrix).
// ---------------------------------------------------------------------------
#define HTILE_B (128 * 144)              // 18432 bytes per operand tile
#define HSTAGE_B (2 * HTILE_B)           // 36864 per stage (A+B)
#define NSTG 3
#define GEMM_SMEM (NSTG * HSTAGE_B)      // 110592

__global__ __launch_bounds__(256, 2) void gemm_h(
    const __half* __restrict__ A, int lda,
    const __half* __restrict__ B, int ldb,
    const void* __restrict__ Resv,
    void* __restrict__ Cv, int ldc, int K, int mode)
{
    extern __shared__ __align__(1024) char sm[];
    const uint32_t sbase = smem_u32(sm);
    const int tid  = threadIdx.x;
    const int wid  = tid >> 5, lane = tid & 31;
    const int g    = lane >> 2, t4 = lane & 3;
    const int wm0  = (wid >> 2) * 64;
    const int wn0  = (wid & 3) * 32;
    const int m0   = blockIdx.y * 128;
    const int n0   = blockIdx.x * 128;

    const int j   = lane & 7;
    const int sel = lane >> 3;
    uint32_t offA[4], offB[2];
    #pragma unroll
    for (int mi = 0; mi < 4; mi++)
        offA[mi] = (uint32_t)((wm0 + mi * 16 + (sel & 1) * 8 + j) * 144 + (sel >> 1) * 16);
    #pragma unroll
    for (int np = 0; np < 2; np++)
        offB[np] = (uint32_t)((wn0 + np * 16 + (sel >> 1) * 8 + j) * 144 + (sel & 1) * 16);

    // cp.async map: 128 rows x 8 segs(16B) per operand; 2 threads/row, 4 segs each
    const int r0 = tid >> 1;
    const int sg = (tid & 1) * 4;
    const __half* Ab = A + (size_t)(m0 + r0) * lda + sg * 8;
    const __half* Bb = B + (size_t)(n0 + r0) * ldb + sg * 8;
    const uint32_t soff = (uint32_t)(r0 * 144 + sg * 16);

    float acc[4][4][4];
    #pragma unroll
    for (int mi = 0; mi < 4; mi++)
        #pragma unroll
        for (int ni = 0; ni < 4; ni++)
            #pragma unroll
            for (int jj = 0; jj < 4; jj++) acc[mi][ni][jj] = 0.0f;

    const int NC = K / 64;

    // prologue: chunks 0 and 1 into stages 0 and 1 (separate commit groups)
    #pragma unroll
    for (int p = 0; p < 2; p++) {
        const uint32_t sA = sbase + p * HSTAGE_B + soff;
        const uint32_t sB = sA + HTILE_B;
        const __half* An = Ab + (size_t)p * 64;
        const __half* Bn = Bb + (size_t)p * 64;
        #pragma unroll
        for (int t = 0; t < 4; t++) {
            cp_async16(sA + t * 16, An + t * 8);
            cp_async16(sB + t * 16, Bn + t * 8);
        }
        CP_COMMIT();
    }

    int stg = 0;          // stage holding chunk c
    for (int c = 0; c < NC; c++) {
        if (c + 2 < NC) CP_WAIT1(); else CP_WAIT0();
        __syncthreads();

        if (c + 2 < NC) {   // issue chunk c+2 into the stage after next
            int s2 = stg + 2; if (s2 >= NSTG) s2 -= NSTG;
            const uint32_t sA = sbase + s2 * HSTAGE_B + soff;
            const uint32_t sB = sA + HTILE_B;
            const __half* An = Ab + (size_t)(c + 2) * 64;
            const __half* Bn = Bb + (size_t)(c + 2) * 64;
            #pragma unroll
            for (int t = 0; t < 4; t++) {
                cp_async16(sA + t * 16, An + t * 8);
                cp_async16(sB + t * 16, Bn + t * 8);
            }
            CP_COMMIT();
        }

        const uint32_t stA = sbase + stg * HSTAGE_B;
        const uint32_t stB = stA + HTILE_B;

        #pragma unroll
        for (int ks = 0; ks < 4; ks++) {      // 4 k-steps of k16
            uint32_t ua[4][4], ub[4][2];
            #pragma unroll
            for (int mi = 0; mi < 4; mi++)
                LDSM_X4(ua[mi][0], ua[mi][1], ua[mi][2], ua[mi][3],
                        stA + offA[mi] + ks * 32);
            #pragma unroll
            for (int np = 0; np < 2; np++)
                LDSM_X4(ub[2*np][0], ub[2*np][1], ub[2*np+1][0], ub[2*np+1][1],
                        stB + offB[np] + ks * 32);
            #pragma unroll
            for (int mi = 0; mi < 4; mi++)
                #pragma unroll
                for (int ni = 0; ni < 4; ni++)
                    mma_f16(acc[mi][ni], ua[mi], ub[ni]);
        }
        __syncthreads();
        if (++stg == NSTG) stg = 0;
    }

    const float qscale = (mode == 3 && n0 < 2048) ? ATT_SCALE : 1.0f;
    float* Cf = (float*)Cv;
    __half* Ch = (__half*)Cv;
    const float*  Rf = (const float*)Resv;
    const __half* Rh = (const __half*)Resv;

    #pragma unroll
    for (int mi = 0; mi < 4; mi++) {
        #pragma unroll
        for (int ni = 0; ni < 4; ni++) {
            const int row = m0 + wm0 + mi * 16 + g;
            const int col = n0 + wn0 + ni * 8 + 2 * t4;
            float2 v0 = make_float2(acc[mi][ni][0], acc[mi][ni][1]);
            float2 v1 = make_float2(acc[mi][ni][2], acc[mi][ni][3]);
            if (mode == 0) {
                *(half2*)(Ch + (size_t)row * ldc + col)       = __floats2half2_rn(v0.x, v0.y);
                *(half2*)(Ch + (size_t)(row + 8) * ldc + col) = __floats2half2_rn(v1.x, v1.y);
            } else if (mode == 1) {
                float2 e0 = *(const float2*)(Rf + (size_t)row * ldc + col);
                float2 e1 = *(const float2*)(Rf + (size_t)(row + 8) * ldc + col);
                v0.x += e0.x; v0.y += e0.y;
                v1.x += e1.x; v1.y += e1.y;
                *(float2*)(Cf + (size_t)row * ldc + col)       = v0;
                *(float2*)(Cf + (size_t)(row + 8) * ldc + col) = v1;
            } else if (mode == 2) {
                half2 h0 = *(const half2*)(Rh + (size_t)row * ldc + col);
                half2 h1 = *(const half2*)(Rh + (size_t)(row + 8) * ldc + col);
                float2 e0 = __half22float2(h0);
                float2 e1 = __half22float2(h1);
                *(half2*)(Ch + (size_t)row * ldc + col) =
                    __floats2half2_rn(silu_f(e0.x) * v0.x, silu_f(e0.y) * v0.y);
                *(half2*)(Ch + (size_t)(row + 8) * ldc + col) =
                    __floats2half2_rn(silu_f(e1.x) * v1.x, silu_f(e1.y) * v1.y);
            } else {
                *(half2*)(Ch + (size_t)row * ldc + col) =
                    __floats2half2_rn(v0.x * qscale, v0.y * qscale);
                *(half2*)(Ch + (size_t)(row + 8) * ldc + col) =
                    __floats2half2_rn(v1.x * qscale, v1.y * qscale);
            }
        }
    }
}

// ---------------------------------------------------------------------------
// RMSNorm: float in -> fp16 out
// ---------------------------------------------------------------------------
__global__ __launch_bounds__(256) void rmsnorm_k(
    const float* __restrict__ x, const float* __restrict__ w, __half* __restrict__ y)
{
    const int row = blockIdx.x;
    const float4* xr = (const float4*)(x + (size_t)row * H_DIM);
    half2* yr = (half2*)(y + (size_t)row * H_DIM);
    const float4* w4 = (const float4*)w;
    const int tid = threadIdx.x;

    float4 v0 = xr[tid];
    float4 v1 = xr[tid + 256];
    float s = v0.x*v0.x + v0.y*v0.y + v0.z*v0.z + v0.w*v0.w
            + v1.x*v1.x + v1.y*v1.y + v1.z*v1.z + v1.w*v1.w;

    #pragma unroll
    for (int off = 16; off; off >>= 1) s += __shfl_xor_sync(0xffffffffu, s, off);

    __shared__ float red[8];
    if ((tid & 31) == 0) red[tid >> 5] = s;
    __syncthreads();
    float tot = red[0] + red[1] + red[2] + red[3] + red[4] + red[5] + red[6] + red[7];
    const float inv = rsqrtf(tot * (1.0f / H_DIM) + 1e-6f);

    float4 w0 = w4[tid], w1 = w4[tid + 256];
    yr[2*tid]           = __floats2half2_rn(v0.x * inv * w0.x, v0.y * inv * w0.y);
    yr[2*tid + 1]       = __floats2half2_rn(v0.z * inv * w0.z, v0.w * inv * w0.w);
    yr[2*(tid+256)]     = __floats2half2_rn(v1.x * inv * w1.x, v1.y * inv * w1.y);
    yr[2*(tid+256) + 1] = __floats2half2_rn(v1.z * inv * w1.z, v1.w * inv * w1.w);
}

// ---------------------------------------------------------------------------
// fp16 tensor-core causal flash attention, GQA kvh = h>>1. (unchanged R12)
// ---------------------------------------------------------------------------
#define QP 136    // halves per Q/K row (272B = 17*16B)
#define VP 72     // halves per Vt/P row (144B = 9*16B)
#define FLASH_SMEM ((128*QP + 2*64*QP + 128*VP + 128*VP) * 2)   // 106496

__global__ __launch_bounds__(256, 1) void flash_h(
    const __half* __restrict__ qkv, __half* __restrict__ out)
{
    extern __shared__ __half smh[];
    __half* Qs  = smh;                   // [128][136]
    __half* Ks  = Qs + 128 * QP;         // [2][64][136]
    __half* Vts = Ks + 2 * 64 * QP;      // [128][72]  d-major (transposed V)
    __half* Ps  = Vts + 128 * VP;        // [128][72]

    const int qt = gridDim.x - 1 - blockIdx.x;
    const int h  = blockIdx.y;
    const int b  = blockIdx.z;
    const int kvh = h >> 1;
    const int q0 = qt * 128;
    const int tid = threadIdx.x;
    const int wid = tid >> 5, lane = tid & 31;
    const int g = lane >> 2, t4 = lane & 3;
    const int j = lane & 7, sel = lane >> 3;
    const int wm0 = wid * 16;

    const __half* qbase = qkv + ((size_t)(b * S_LEN + q0)) * QKV_LD + h * HD;
    const __half* kbase = qkv + ((size_t)(b * S_LEN)) * QKV_LD + 2048 + kvh * HD;
    const __half* vbase = kbase + 1024;

    // Load Q tile (128 rows x 16 segs of 16B)
    #pragma unroll
    for (int t = 0; t < 8; t++) {
        int idx = tid + t * 256;
        int r = idx >> 4;
        int seg = idx & 15;
        *(uint4*)&Qs[r * QP + seg * 8] = *(const uint4*)(qbase + (size_t)r * QKV_LD + seg * 8);
    }

    const uint32_t sQ = smem_u32(Qs), sKb = smem_u32(Ks);
    const uint32_t sV = smem_u32(Vts), sP = smem_u32(Ps);

    // K cp.async map: 64 rows x 16 segs(16B); 4 threads/row, 4 segs each
    const int kr  = tid >> 2;
    const int ksg = (tid & 3) * 4;

    // ldmatrix lane byte-offsets
    const uint32_t offQA = (uint32_t)((wm0 + (sel & 1) * 8 + j) * (QP * 2) + (sel >> 1) * 16);
    uint32_t offKB[4];
    #pragma unroll
    for (int np = 0; np < 4; np++)
        offKB[np] = (uint32_t)((np * 16 + (sel >> 1) * 8 + j) * (QP * 2) + (sel & 1) * 16);
    const uint32_t offPA = (uint32_t)((wm0 + (sel & 1) * 8 + j) * (VP * 2) + (sel >> 1) * 16);
    uint32_t offVB[8];
    #pragma unroll
    for (int np = 0; np < 8; np++)
        offVB[np] = (uint32_t)((np * 16 + (sel >> 1) * 8 + j) * (VP * 2) + (sel & 1) * 16);

    float m0 = -1e30f, m1 = -1e30f, l0 = 0.0f, l1 = 0.0f;
    float o[16][4];
    #pragma unroll
    for (int nt = 0; nt < 16; nt++)
        #pragma unroll
        for (int c = 0; c < 4; c++) o[nt][c] = 0.0f;

    const int nkt = 2 * qt + 2;
    uint4 vreg[4];

    // ---- prologue: K0 via cp.async (full 16 segs/row), V0 via registers ----
    {
        const uint32_t dK = sKb + (uint32_t)(kr * (QP * 2));
        const __half* srcK = kbase + (size_t)kr * QKV_LD;
        #pragma unroll
        for (int t = 0; t < 4; t++)
            cp_async16(dK + (ksg + t) * 16, srcK + (ksg + t) * 8);
        CP_COMMIT();
        #pragma unroll
        for (int t = 0; t < 4; t++) {
            int idx = tid + t * 256;
            int r = idx >> 4;
            int seg = idx & 15;
            vreg[t] = *(const uint4*)(vbase + (size_t)r * QKV_LD + seg * 8);
        }
        CP_WAIT0();
        __syncthreads();
        #pragma unroll
        for (int t = 0; t < 4; t++) {
            int idx = tid + t * 256;
            int r = idx >> 4;
            int dbase = (idx & 15) * 8;
            const __half* hh = (const __half*)&vreg[t];
            #pragma unroll
            for (int i = 0; i < 8; i++) Vts[(dbase + i) * VP + r] = hh[i];
        }
        __syncthreads();
    }

    int cur = 0;
    for (int kt = 0; kt < nkt; kt++) {
        if (kt + 1 < nkt) {
            const int k1 = (kt + 1) * 64;
            const uint32_t dK = sKb + (uint32_t)((1 - cur) * 64 * QP * 2 + kr * (QP * 2));
            const __half* srcK = kbase + (size_t)(k1 + kr) * QKV_LD;
            #pragma unroll
            for (int t = 0; t < 4; t++)
                cp_async16(dK + (ksg + t) * 16, srcK + (ksg + t) * 8);
            CP_COMMIT();
            #pragma unroll
            for (int t = 0; t < 4; t++) {
                int idx = tid + t * 256;
                int r = idx >> 4;
                int seg = idx & 15;
                vreg[t] = *(const uint4*)(vbase + (size_t)(k1 + r) * QKV_LD + seg * 8);
            }
        }

        const int k0 = kt * 64;
        const uint32_t sK = sKb + (uint32_t)(cur * 64 * QP * 2);

        // --- S = Q K^T (16 q-rows x 64 k-cols per warp), HD/16 = 8 k-steps ---
        float s[8][4];
        #pragma unroll
        for (int nt = 0; nt < 8; nt++)
            #pragma unroll
            for (int c = 0; c < 4; c++) s[nt][c] = 0.0f;

        #pragma unroll
        for (int ks = 0; ks < 8; ks++) {
            uint32_t a[4], bb[8][2];
            LDSM_X4(a[0], a[1], a[2], a[3], sQ + offQA + ks * 32);
            #pragma unroll
            for (int np = 0; np < 4; np++)
                LDSM_X4(bb[2*np][0], bb[2*np][1], bb[2*np+1][0], bb[2*np+1][1],
                        sK + offKB[np] + ks * 32);
            #pragma unroll
            for (int nt = 0; nt < 8; nt++)
                mma_f16(s[nt], a, bb[nt]);
        }

        // --- causal mask (last two k-tiles only) ---
        if (kt >= 2 * qt) {
            const int r0g = q0 + wm0 + g;
            const int r1g = r0g + 8;
            #pragma unroll
            for (int nt = 0; nt < 8; nt++) {
                const int c0 = k0 + nt * 8 + 2 * t4;
                const int c1 = c0 + 1;
                if (c0 > r0g) s[nt][0] = -1e30f;
                if (c1 > r0g) s[nt][1] = -1e30f;
                if (c0 > r1g) s[nt][2] = -1e30f;
                if (c1 > r1g) s[nt][3] = -1e30f;
            }
        }

        // --- online softmax ---
        float mx0 = -1e30f, mx1 = -1e30f;
        #pragma unroll
        for (int nt = 0; nt < 8; nt++) {
            mx0 = fmaxf(mx0, fmaxf(s[nt][0], s[nt][1]));
            mx1 = fmaxf(mx1, fmaxf(s[nt][2], s[nt][3]));
        }
        mx0 = fmaxf(mx0, __shfl_xor_sync(0xffffffffu, mx0, 1));
        mx0 = fmaxf(mx0, __shfl_xor_sync(0xffffffffu, mx0, 2));
        mx1 = fmaxf(mx1, __shfl_xor_sync(0xffffffffu, mx1, 1));
        mx1 = fmaxf(mx1, __shfl_xor_sync(0xffffffffu, mx1, 2));

        const float nm0 = fmaxf(m0, mx0);
        const float nm1 = fmaxf(m1, mx1);
        const float al0 = __expf(m0 - nm0);
        const float al1 = __expf(m1 - nm1);
        m0 = nm0; m1 = nm1;

        float rs0 = 0.0f, rs1 = 0.0f;
        const int prow0 = (wm0 + g) * VP + 2 * t4;
        const int prow1 = (wm0 + g + 8) * VP + 2 * t4;
        #pragma unroll
        for (int nt = 0; nt < 8; nt++) {
            float p0 = __expf(s[nt][0] - nm0);
            float p1 = __expf(s[nt][1] - nm0);
            float p2 = __expf(s[nt][2] - nm1);
            float p3 = __expf(s[nt][3] - nm1);
            rs0 += p0 + p1;
            rs1 += p2 + p3;
            *(half2*)&Ps[prow0 + nt * 8] = __floats2half2_rn(p0, p1);
            *(half2*)&Ps[prow1 + nt * 8] = __floats2half2_rn(p2, p3);
        }
        rs0 += __shfl_xor_sync(0xffffffffu, rs0, 1);
        rs0 += __shfl_xor_sync(0xffffffffu, rs0, 2);
        rs1 += __shfl_xor_sync(0xffffffffu, rs1, 1);
        rs1 += __shfl_xor_sync(0xffffffffu, rs1, 2);
        l0 = l0 * al0 + rs0;
        l1 = l1 * al1 + rs1;

        #pragma unroll
        for (int nt = 0; nt < 16; nt++) {
            o[nt][0] *= al0; o[nt][1] *= al0;
            o[nt][2] *= al1; o[nt][3] *= al1;
        }
        __syncwarp();   // Ps rows are warp-private: order stores before ldmatrix

        // --- O += P V (16 q-rows x 128 d-cols per warp), 64/16 = 4 k-steps ---
        #pragma unroll
        for (int ks = 0; ks < 4; ks++) {
            uint32_t pa[4], vb[16][2];
            LDSM_X4(pa[0], pa[1], pa[2], pa[3], sP + offPA + ks * 32);
            #pragma unroll
            for (int np = 0; np < 8; np++)
                LDSM_X4(vb[2*np][0], vb[2*np][1], vb[2*np+1][0], vb[2*np+1][1],
                        sV + offVB[np] + ks * 32);
            #pragma unroll
            for (int nt = 0; nt < 16; nt++)
                mma_f16(o[nt], pa, vb[nt]);
        }

        __syncthreads();   // all warps done reading Vts
        if (kt + 1 < nkt) {
            #pragma unroll
            for (int t = 0; t < 4; t++) {
                int idx = tid + t * 256;
                int r = idx >> 4;
                int dbase = (idx & 15) * 8;
                const __half* hh = (const __half*)&vreg[t];
                #pragma unroll
                for (int i = 0; i < 8; i++) Vts[(dbase + i) * VP + r] = hh[i];
            }
            CP_WAIT0();    // next K landed (issued a full iteration ago)
        }
        __syncthreads();
        cur ^= 1;
    }

    // --- normalize and write fp16 (feeds O-proj GEMM) ---
    const float inv0 = 1.0f / l0;
    const float inv1 = 1.0f / l1;
    const size_t row0 = (size_t)(b * S_LEN + q0 + wm0 + g);
    #pragma unroll
    for (int nt = 0; nt < 16; nt++) {
        const int col = h * HD + nt * 8 + 2 * t4;
        *(half2*)(out + row0 * H_DIM + col) =
            __floats2half2_rn(o[nt][0] * inv0, o[nt][1] * inv0);
        *(half2*)(out + (row0 + 8) * H_DIM + col) =
            __floats2half2_rn(o[nt][2] * inv1, o[nt][3] * inv1);
    }
}

// ---------------------------------------------------------------------------
// Launch
// ---------------------------------------------------------------------------
extern "C" void kernel_launch(void* const* d_in, const int* in_sizes, int n_in,
                              void* d_out, int out_size)
{
    const float* hidden = (const float*)d_in[0];
    const float* q_w    = (const float*)d_in[2];
    const float* k_w    = (const float*)d_in[3];
    const float* v_w    = (const float*)d_in[4];
    const float* o_w    = (const float*)d_in[5];
    const float* gate_w = (const float*)d_in[6];
    const float* up_w   = (const float*)d_in[7];
    const float* down_w = (const float*)d_in[8];
    const float* ln1    = (const float*)d_in[9];
    const float* ln2    = (const float*)d_in[10];
    float* out = (float*)d_out;

    __half *xn, *qkv, *attn, *gate, *ff, *wqkv, *wo, *wg, *wu, *wd;
    float *hbuf;
    cudaGetSymbolAddress((void**)&xn,   g_xn);
    cudaGetSymbolAddress((void**)&qkv,  g_qkv);
    cudaGetSymbolAddress((void**)&attn, g_attn);
    cudaGetSymbolAddress((void**)&hbuf, g_h);
    cudaGetSymbolAddress((void**)&gate, g_gate);
    cudaGetSymbolAddress((void**)&ff,   g_ff);
    cudaGetSymbolAddress((void**)&wqkv, g_wqkv);
    cudaGetSymbolAddress((void**)&wo,   g_wo);
    cudaGetSymbolAddress((void**)&wg,   g_wg);
    cudaGetSymbolAddress((void**)&wu,   g_wu);
    cudaGetSymbolAddress((void**)&wd,   g_wd);

    cudaFuncSetAttribute(flash_h, cudaFuncAttributeMaxDynamicSharedMemorySize, FLASH_SMEM);
    cudaFuncSetAttribute(gemm_h,  cudaFuncAttributeMaxDynamicSharedMemorySize, GEMM_SMEM);

    // 0) convert weights to fp16 (q|k|v concatenated); grid-stride ILP
    {
        auto cvt = [](const float* src, __half* dst, size_t n) {
            int n4 = (int)(n / 4);
            int grid = (n4 + 1023) / 1024;       // 4 float4 per thread
            cvt_wh_k<<<grid, 256>>>((const float4*)src, dst, n4);
        };
        cvt(q_w,    wqkv,                       (size_t)2048 * 2048);
        cvt(k_w,    wqkv + (size_t)2048 * 2048, (size_t)1024 * 2048);
        cvt(v_w,    wqkv + (size_t)3072 * 2048, (size_t)1024 * 2048);
        cvt(o_w,    wo, (size_t)2048 * 2048);
        cvt(gate_w, wg, (size_t)FF_DIM * 2048);
        cvt(up_w,   wu, (size_t)FF_DIM * 2048);
        cvt(down_w, wd, (size_t)2048 * FF_DIM);
    }

    // 1) rmsnorm(hidden) -> xn (fp16)
    rmsnorm_k<<<MROWS, 256>>>(hidden, ln1, xn);

    // 2) fused QKV projection -> qkv (fp16, q pre-scaled)
    gemm_h<<<dim3(32, 32), 256, GEMM_SMEM>>>(xn, H_DIM, wqkv, H_DIM, nullptr,
                                             qkv, QKV_LD, H_DIM, 3);

    // 3) fp16 tensor-core causal flash attention -> attn
    flash_h<<<dim3(S_LEN / 128, NHEADS, B_SZ), 256, FLASH_SMEM>>>(qkv, attn);

    // 4) O projection + residual -> hbuf (fp32)
    gemm_h<<<dim3(16, 32), 256, GEMM_SMEM>>>(attn, H_DIM, wo, H_DIM, hidden,
                                             hbuf, H_DIM, H_DIM, 1);

    // 5) rmsnorm(hbuf) -> xn (fp16)
    rmsnorm_k<<<MROWS, 256>>>(hbuf, ln2, xn);

    // 6) gate projection -> gate (fp16 raw)
    gemm_h<<<dim3(44, 32), 256, GEMM_SMEM>>>(xn, H_DIM, wg, H_DIM, nullptr,
                                             gate, FF_DIM, H_DIM, 0);

    // 7) up projection + fused SwiGLU -> ff = h(silu(gate)*up) (fp16)
    gemm_h<<<dim3(44, 32), 256, GEMM_SMEM>>>(xn, H_DIM, wu, H_DIM, gate,
                                             ff, FF_DIM, H_DIM, 2);

    // 8) down projection + residual -> out (fp32)
    gemm_h<<<dim3(16, 32), 256, GEMM_SMEM>>>(ff, FF_DIM, wd, FF_DIM, hbuf,
                                             out, H_DIM, FF_DIM, 1);
}

// round 14
// speedup vs baseline: 1.0003x; 1.0003x over previous
#include <cuda_runtime.h>
#include <cuda_fp16.h>
#include <cstdint>
#include <cstddef>

// Problem constants
#define H_DIM   2048
#define S_LEN   2048
#define B_SZ    2
#define NHEADS  16
#define NKVH    8
#define HD      128
#define FF_DIM  5632
#define MROWS   (B_SZ * S_LEN)          // 4096
#define QKV_LD  4096                    // q(2048) | k(1024) | v(1024)
#define ATT_SCALE 0.08838834764831845f  // 1/sqrt(128)

// ---------------------------------------------------------------------------
// Scratch (activations fp16; residual stream fp32)
// ---------------------------------------------------------------------------
__device__ __half g_xn  [(size_t)MROWS * H_DIM];
__device__ __half g_qkv [(size_t)MROWS * QKV_LD];
__device__ __half g_attn[(size_t)MROWS * H_DIM];
__device__ float  g_h   [(size_t)MROWS * H_DIM];
__device__ __half g_gate[(size_t)MROWS * FF_DIM];
__device__ __half g_ff  [(size_t)MROWS * FF_DIM];
// fp16 weight copies
__device__ __half g_wqkv[(size_t)4096 * 2048];
__device__ __half g_wo[(size_t)2048 * 2048];
__device__ __half g_wg[(size_t)FF_DIM * 2048];
__device__ __half g_wu[(size_t)FF_DIM * 2048];
__device__ __half g_wd[(size_t)2048 * FF_DIM];

// ---------------------------------------------------------------------------
// Helpers (family-portable PTX: cp.async + mma.sync + ldmatrix)
// ---------------------------------------------------------------------------
__device__ __forceinline__ uint32_t smem_u32(const void* p) {
    uint32_t a;
    asm("{ .reg .u64 t; cvta.to.shared.u64 t, %1; cvt.u32.u64 %0, t; }"
        : "=r"(a) : "l"(p));
    return a;
}

__device__ __forceinline__ void cp_async16(uint32_t dst, const void* src) {
    asm volatile("cp.async.cg.shared.global [%0], [%1], 16;"
                 :: "r"(dst), "l"(src) : "memory");
}
#define CP_COMMIT() asm volatile("cp.async.commit_group;" ::: "memory")
#define CP_WAIT0()  asm volatile("cp.async.wait_group 0;" ::: "memory")

#define LDSM_X4(r0, r1, r2, r3, addr)                                        \
    asm volatile("ldmatrix.sync.aligned.m8n8.x4.shared.b16 {%0,%1,%2,%3}, [%4];" \
        : "=r"(r0), "=r"(r1), "=r"(r2), "=r"(r3) : "r"(addr))

// m16n8k16 fp16 MMA, fp32 accumulate (sm_80+ family-portable)
__device__ __forceinline__ void mma_f16(float* d, const uint32_t* a, const uint32_t* b) {
    asm volatile(
        "mma.sync.aligned.m16n8k16.row.col.f32.f16.f16.f32 "
        "{%0,%1,%2,%3}, {%4,%5,%6,%7}, {%8,%9}, {%0,%1,%2,%3};"
        : "+f"(d[0]), "+f"(d[1]), "+f"(d[2]), "+f"(d[3])
        : "r"(a[0]), "r"(a[1]), "r"(a[2]), "r"(a[3]), "r"(b[0]), "r"(b[1]));
}

__device__ __forceinline__ float silu_f(float x) {
    return x / (1.0f + __expf(-x));
}

// ---------------------------------------------------------------------------
// Weight convert: float -> fp16 (grid-stride)
// ---------------------------------------------------------------------------
__global__ __launch_bounds__(256) void cvt_wh_k(
    const float4* __restrict__ in, __half* __restrict__ out, int n4)
{
    const int stride = gridDim.x * 256;
    for (int i = blockIdx.x * 256 + threadIdx.x; i < n4; i += stride) {
        float4 v = in[i];
        half2* o = (half2*)(out + (size_t)i * 4);
        o[0] = __floats2half2_rn(v.x, v.y);
        o[1] = __floats2half2_rn(v.z, v.w);
    }
}

// ---------------------------------------------------------------------------
// fp16 tensor-core NT GEMM: C[m,n] = sum_k A[m,k]*B[n,k], epilogue modes:
//  0: half  C = h(acc)                   (raw half; used for gate)
//  1: float C = acc + Res(float)
//  2: half  C = h( silu(Res:half) * acc ) (fused SwiGLU; Res = gate fp16)
//  3: half  C = h( acc * (n0<2048 ? ATT_SCALE : 1) )  (fused QKV post)
// BM=BN=128, BK=64 halves, 8 warps (2x4), warp tile 64x32.
// 2-stage cp.async double buffer (R12-proven).
// Smem rows padded to 72 halves (144B = 9x16B, conflict-free ldmatrix).
// ---------------------------------------------------------------------------
#define HTILE_B (128 * 144)              // 18432 bytes per operand tile
#define HSTAGE_B (2 * HTILE_B)           // 36864 per stage (A+B)
#define GEMM_SMEM (2 * HSTAGE_B)         // 73728

__global__ __launch_bounds__(256, 2) void gemm_h(
    const __half* __restrict__ A, int lda,
    const __half* __restrict__ B, int ldb,
    const void* __restrict__ Resv,
    void* __restrict__ Cv, int ldc, int K, int mode)
{
    extern __shared__ __align__(1024) char sm[];
    const uint32_t sbase = smem_u32(sm);
    const int tid  = threadIdx.x;
    const int wid  = tid >> 5, lane = tid & 31;
    const int g    = lane >> 2, t4 = lane & 3;
    const int wm0  = (wid >> 2) * 64;
    const int wn0  = (wid & 3) * 32;
    const int m0   = blockIdx.y * 128;
    const int n0   = blockIdx.x * 128;

    const int j   = lane & 7;
    const int sel = lane >> 3;
    uint32_t offA[4], offB[2];
    #pragma unroll
    for (int mi = 0; mi < 4; mi++)
        offA[mi] = (uint32_t)((wm0 + mi * 16 + (sel & 1) * 8 + j) * 144 + (sel >> 1) * 16);
    #pragma unroll
    for (int np = 0; np < 2; np++)
        offB[np] = (uint32_t)((wn0 + np * 16 + (sel >> 1) * 8 + j) * 144 + (sel & 1) * 16);

    // cp.async map: 128 rows x 8 segs(16B) per operand; 2 threads/row, 4 segs each
    const int r0 = tid >> 1;
    const int sg = (tid & 1) * 4;
    const __half* Ab = A + (size_t)(m0 + r0) * lda + sg * 8;
    const __half* Bb = B + (size_t)(n0 + r0) * ldb + sg * 8;
    const uint32_t soff = (uint32_t)(r0 * 144 + sg * 16);

    float acc[4][4][4];
    #pragma unroll
    for (int mi = 0; mi < 4; mi++)
        #pragma unroll
        for (int ni = 0; ni < 4; ni++)
            #pragma unroll
            for (int jj = 0; jj < 4; jj++) acc[mi][ni][jj] = 0.0f;

    const int NC = K / 64;

    {
        const uint32_t sA = sbase + soff;
        const uint32_t sB = sA + HTILE_B;
        #pragma unroll
        for (int t = 0; t < 4; t++) {
            cp_async16(sA + t * 16, Ab + t * 8);
            cp_async16(sB + t * 16, Bb + t * 8);
        }
        CP_COMMIT();
    }

    for (int c = 0; c < NC; c++) {
        CP_WAIT0();
        __syncthreads();

        if (c + 1 < NC) {
            const uint32_t sA = sbase + ((c + 1) & 1) * HSTAGE_B + soff;
            const uint32_t sB = sA + HTILE_B;
            const __half* An = Ab + (size_t)(c + 1) * 64;
            const __half* Bn = Bb + (size_t)(c + 1) * 64;
            #pragma unroll
            for (int t = 0; t < 4; t++) {
                cp_async16(sA + t * 16, An + t * 8);
                cp_async16(sB + t * 16, Bn + t * 8);
            }
            CP_COMMIT();
        }

        const uint32_t stA = sbase + (c & 1) * HSTAGE_B;
        const uint32_t stB = stA + HTILE_B;

        #pragma unroll
        for (int ks = 0; ks < 4; ks++) {      // 4 k-steps of k16
            uint32_t ua[4][4], ub[4][2];
            #pragma unroll
            for (int mi = 0; mi < 4; mi++)
                LDSM_X4(ua[mi][0], ua[mi][1], ua[mi][2], ua[mi][3],
                        stA + offA[mi] + ks * 32);
            #pragma unroll
            for (int np = 0; np < 2; np++)
                LDSM_X4(ub[2*np][0], ub[2*np][1], ub[2*np+1][0], ub[2*np+1][1],
                        stB + offB[np] + ks * 32);
            #pragma unroll
            for (int mi = 0; mi < 4; mi++)
                #pragma unroll
                for (int ni = 0; ni < 4; ni++)
                    mma_f16(acc[mi][ni], ua[mi], ub[ni]);
        }
        __syncthreads();
    }

    const float qscale = (mode == 3 && n0 < 2048) ? ATT_SCALE : 1.0f;
    float* Cf = (float*)Cv;
    __half* Ch = (__half*)Cv;
    const float*  Rf = (const float*)Resv;
    const __half* Rh = (const __half*)Resv;

    #pragma unroll
    for (int mi = 0; mi < 4; mi++) {
        #pragma unroll
        for (int ni = 0; ni < 4; ni++) {
            const int row = m0 + wm0 + mi * 16 + g;
            const int col = n0 + wn0 + ni * 8 + 2 * t4;
            float2 v0 = make_float2(acc[mi][ni][0], acc[mi][ni][1]);
            float2 v1 = make_float2(acc[mi][ni][2], acc[mi][ni][3]);
            if (mode == 0) {
                *(half2*)(Ch + (size_t)row * ldc + col)       = __floats2half2_rn(v0.x, v0.y);
                *(half2*)(Ch + (size_t)(row + 8) * ldc + col) = __floats2half2_rn(v1.x, v1.y);
            } else if (mode == 1) {
                float2 e0 = *(const float2*)(Rf + (size_t)row * ldc + col);
                float2 e1 = *(const float2*)(Rf + (size_t)(row + 8) * ldc + col);
                v0.x += e0.x; v0.y += e0.y;
                v1.x += e1.x; v1.y += e1.y;
                *(float2*)(Cf + (size_t)row * ldc + col)       = v0;
                *(float2*)(Cf + (size_t)(row + 8) * ldc + col) = v1;
            } else if (mode == 2) {
                half2 h0 = *(const half2*)(Rh + (size_t)row * ldc + col);
                half2 h1 = *(const half2*)(Rh + (size_t)(row + 8) * ldc + col);
                float2 e0 = __half22float2(h0);
                float2 e1 = __half22float2(h1);
                *(half2*)(Ch + (size_t)row * ldc + col) =
                    __floats2half2_rn(silu_f(e0.x) * v0.x, silu_f(e0.y) * v0.y);
                *(half2*)(Ch + (size_t)(row + 8) * ldc + col) =
                    __floats2half2_rn(silu_f(e1.x) * v1.x, silu_f(e1.y) * v1.y);
            } else {
                *(half2*)(Ch + (size_t)row * ldc + col) =
                    __floats2half2_rn(v0.x * qscale, v0.y * qscale);
                *(half2*)(Ch + (size_t)(row + 8) * ldc + col) =
                    __floats2half2_rn(v1.x * qscale, v1.y * qscale);
            }
        }
    }
}

// ---------------------------------------------------------------------------
// RMSNorm: float in -> fp16 out
// ---------------------------------------------------------------------------
__global__ __launch_bounds__(256) void rmsnorm_k(
    const float* __restrict__ x, const float* __restrict__ w, __half* __restrict__ y)
{
    const int row = blockIdx.x;
    const float4* xr = (const float4*)(x + (size_t)row * H_DIM);
    half2* yr = (half2*)(y + (size_t)row * H_DIM);
    const float4* w4 = (const float4*)w;
    const int tid = threadIdx.x;

    float4 v0 = xr[tid];
    float4 v1 = xr[tid + 256];
    float s = v0.x*v0.x + v0.y*v0.y + v0.z*v0.z + v0.w*v0.w
            + v1.x*v1.x + v1.y*v1.y + v1.z*v1.z + v1.w*v1.w;

    #pragma unroll
    for (int off = 16; off; off >>= 1) s += __shfl_xor_sync(0xffffffffu, s, off);

    __shared__ float red[8];
    if ((tid & 31) == 0) red[tid >> 5] = s;
    __syncthreads();
    float tot = red[0] + red[1] + red[2] + red[3] + red[4] + red[5] + red[6] + red[7];
    const float inv = rsqrtf(tot * (1.0f / H_DIM) + 1e-6f);

    float4 w0 = w4[tid], w1 = w4[tid + 256];
    yr[2*tid]           = __floats2half2_rn(v0.x * inv * w0.x, v0.y * inv * w0.y);
    yr[2*tid + 1]       = __floats2half2_rn(v0.z * inv * w0.z, v0.w * inv * w0.w);
    yr[2*(tid+256)]     = __floats2half2_rn(v1.x * inv * w1.x, v1.y * inv * w1.y);
    yr[2*(tid+256) + 1] = __floats2half2_rn(v1.z * inv * w1.z, v1.w * inv * w1.w);
}

// ---------------------------------------------------------------------------
// fp16 tensor-core causal flash attention, GQA kvh = h>>1.
// NOW 2 CTAs/SM (2 x 104KB smem = 208KB <= 228KB): one CTA's MMA phase hides
// the other's softmax/transpose/sync latency; waves 3.46 -> 1.73.
// ---------------------------------------------------------------------------
#define QP 136    // halves per Q/K row (272B = 17*16B)
#define VP 72     // halves per Vt/P row (144B = 9*16B)
#define FLASH_SMEM ((128*QP + 2*64*QP + 128*VP + 128*VP) * 2)   // 106496

__global__ __launch_bounds__(256, 2) void flash_h(
    const __half* __restrict__ qkv, __half* __restrict__ out)
{
    extern __shared__ __half smh[];
    __half* Qs  = smh;                   // [128][136]
    __half* Ks  = Qs + 128 * QP;         // [2][64][136]
    __half* Vts = Ks + 2 * 64 * QP;      // [128][72]  d-major (transposed V)
    __half* Ps  = Vts + 128 * VP;        // [128][72]

    const int qt = gridDim.x - 1 - blockIdx.x;
    const int h  = blockIdx.y;
    const int b  = blockIdx.z;
    const int kvh = h >> 1;
    const int q0 = qt * 128;
    const int tid = threadIdx.x;
    const int wid = tid >> 5, lane = tid & 31;
    const int g = lane >> 2, t4 = lane & 3;
    const int j = lane & 7, sel = lane >> 3;
    const int wm0 = wid * 16;

    const __half* qbase = qkv + ((size_t)(b * S_LEN + q0)) * QKV_LD + h * HD;
    const __half* kbase = qkv + ((size_t)(b * S_LEN)) * QKV_LD + 2048 + kvh * HD;
    const __half* vbase = kbase + 1024;

    // Load Q tile (128 rows x 16 segs of 16B)
    #pragma unroll
    for (int t = 0; t < 8; t++) {
        int idx = tid + t * 256;
        int r = idx >> 4;
        int seg = idx & 15;
        *(uint4*)&Qs[r * QP + seg * 8] = *(const uint4*)(qbase + (size_t)r * QKV_LD + seg * 8);
    }

    const uint32_t sQ = smem_u32(Qs), sKb = smem_u32(Ks);
    const uint32_t sV = smem_u32(Vts), sP = smem_u32(Ps);

    // K cp.async map: 64 rows x 16 segs(16B); 4 threads/row, 4 segs each
    const int kr  = tid >> 2;
    const int ksg = (tid & 3) * 4;

    // ldmatrix lane byte-offsets
    const uint32_t offQA = (uint32_t)((wm0 + (sel & 1) * 8 + j) * (QP * 2) + (sel >> 1) * 16);
    uint32_t offKB[4];
    #pragma unroll
    for (int np = 0; np < 4; np++)
        offKB[np] = (uint32_t)((np * 16 + (sel >> 1) * 8 + j) * (QP * 2) + (sel & 1) * 16);
    const uint32_t offPA = (uint32_t)((wm0 + (sel & 1) * 8 + j) * (VP * 2) + (sel >> 1) * 16);
    uint32_t offVB[8];
    #pragma unroll
    for (int np = 0; np < 8; np++)
        offVB[np] = (uint32_t)((np * 16 + (sel >> 1) * 8 + j) * (VP * 2) + (sel & 1) * 16);

    float m0 = -1e30f, m1 = -1e30f, l0 = 0.0f, l1 = 0.0f;
    float o[16][4];
    #pragma unroll
    for (int nt = 0; nt < 16; nt++)
        #pragma unroll
        for (int c = 0; c < 4; c++) o[nt][c] = 0.0f;

    const int nkt = 2 * qt + 2;
    uint4 vreg[4];

    // ---- prologue: K0 via cp.async (full 16 segs/row), V0 via registers ----
    {
        const uint32_t dK = sKb + (uint32_t)(kr * (QP * 2));
        const __half* srcK = kbase + (size_t)kr * QKV_LD;
        #pragma unroll
        for (int t = 0; t < 4; t++)
            cp_async16(dK + (ksg + t) * 16, srcK + (ksg + t) * 8);
        CP_COMMIT();
        #pragma unroll
        for (int t = 0; t < 4; t++) {
            int idx = tid + t * 256;
            int r = idx >> 4;
            int seg = idx & 15;
            vreg[t] = *(const uint4*)(vbase + (size_t)r * QKV_LD + seg * 8);
        }
        CP_WAIT0();
        __syncthreads();
        #pragma unroll
        for (int t = 0; t < 4; t++) {
            int idx = tid + t * 256;
            int r = idx >> 4;
            int dbase = (idx & 15) * 8;
            const __half* hh = (const __half*)&vreg[t];
            #pragma unroll
            for (int i = 0; i < 8; i++) Vts[(dbase + i) * VP + r] = hh[i];
        }
        __syncthreads();
    }

    int cur = 0;
    for (int kt = 0; kt < nkt; kt++) {
        if (kt + 1 < nkt) {
            const int k1 = (kt + 1) * 64;
            const uint32_t dK = sKb + (uint32_t)((1 - cur) * 64 * QP * 2 + kr * (QP * 2));
            const __half* srcK = kbase + (size_t)(k1 + kr) * QKV_LD;
            #pragma unroll
            for (int t = 0; t < 4; t++)
                cp_async16(dK + (ksg + t) * 16, srcK + (ksg + t) * 8);
            CP_COMMIT();
            #pragma unroll
            for (int t = 0; t < 4; t++) {
                int idx = tid + t * 256;
                int r = idx >> 4;
                int seg = idx & 15;
                vreg[t] = *(const uint4*)(vbase + (size_t)(k1 + r) * QKV_LD + seg * 8);
            }
        }

        const int k0 = kt * 64;
        const uint32_t sK = sKb + (uint32_t)(cur * 64 * QP * 2);

        // --- S = Q K^T (16 q-rows x 64 k-cols per warp), HD/16 = 8 k-steps ---
        float s[8][4];
        #pragma unroll
        for (int nt = 0; nt < 8; nt++)
            #pragma unroll
            for (int c = 0; c < 4; c++) s[nt][c] = 0.0f;

        #pragma unroll
        for (int ks = 0; ks < 8; ks++) {
            uint32_t a[4], bb[8][2];
            LDSM_X4(a[0], a[1], a[2], a[3], sQ + offQA + ks * 32);
            #pragma unroll
            for (int np = 0; np < 4; np++)
                LDSM_X4(bb[2*np][0], bb[2*np][1], bb[2*np+1][0], bb[2*np+1][1],
                        sK + offKB[np] + ks * 32);
            #pragma unroll
            for (int nt = 0; nt < 8; nt++)
                mma_f16(s[nt], a, bb[nt]);
        }

        // --- causal mask (last two k-tiles only) ---
        if (kt >= 2 * qt) {
            const int r0g = q0 + wm0 + g;
            const int r1g = r0g + 8;
            #pragma unroll
            for (int nt = 0; nt < 8; nt++) {
                const int c0 = k0 + nt * 8 + 2 * t4;
                const int c1 = c0 + 1;
                if (c0 > r0g) s[nt][0] = -1e30f;
                if (c1 > r0g) s[nt][1] = -1e30f;
                if (c0 > r1g) s[nt][2] = -1e30f;
                if (c1 > r1g) s[nt][3] = -1e30f;
            }
        }

        // --- online softmax ---
        float mx0 = -1e30f, mx1 = -1e30f;
        #pragma unroll
        for (int nt = 0; nt < 8; nt++) {
            mx0 = fmaxf(mx0, fmaxf(s[nt][0], s[nt][1]));
            mx1 = fmaxf(mx1, fmaxf(s[nt][2], s[nt][3]));
        }
        mx0 = fmaxf(mx0, __shfl_xor_sync(0xffffffffu, mx0, 1));
        mx0 = fmaxf(mx0, __shfl_xor_sync(0xffffffffu, mx0, 2));
        mx1 = fmaxf(mx1, __shfl_xor_sync(0xffffffffu, mx1, 1));
        mx1 = fmaxf(mx1, __shfl_xor_sync(0xffffffffu, mx1, 2));

        const float nm0 = fmaxf(m0, mx0);
        const float nm1 = fmaxf(m1, mx1);
        const float al0 = __expf(m0 - nm0);
        const float al1 = __expf(m1 - nm1);
        m0 = nm0; m1 = nm1;

        float rs0 = 0.0f, rs1 = 0.0f;
        const int prow0 = (wm0 + g) * VP + 2 * t4;
        const int prow1 = (wm0 + g + 8) * VP + 2 * t4;
        #pragma unroll
        for (int nt = 0; nt < 8; nt++) {
            float p0 = __expf(s[nt][0] - nm0);
            float p1 = __expf(s[nt][1] - nm0);
            float p2 = __expf(s[nt][2] - nm1);
            float p3 = __expf(s[nt][3] - nm1);
            rs0 += p0 + p1;
            rs1 += p2 + p3;
            *(half2*)&Ps[prow0 + nt * 8] = __floats2half2_rn(p0, p1);
            *(half2*)&Ps[prow1 + nt * 8] = __floats2half2_rn(p2, p3);
        }
        rs0 += __shfl_xor_sync(0xffffffffu, rs0, 1);
        rs0 += __shfl_xor_sync(0xffffffffu, rs0, 2);
        rs1 += __shfl_xor_sync(0xffffffffu, rs1, 1);
        rs1 += __shfl_xor_sync(0xffffffffu, rs1, 2);
        l0 = l0 * al0 + rs0;
        l1 = l1 * al1 + rs1;

        #pragma unroll
        for (int nt = 0; nt < 16; nt++) {
            o[nt][0] *= al0; o[nt][1] *= al0;
            o[nt][2] *= al1; o[nt][3] *= al1;
        }
        __syncwarp();   // Ps rows are warp-private: order stores before ldmatrix

        // --- O += P V (16 q-rows x 128 d-cols per warp), 64/16 = 4 k-steps ---
        #pragma unroll
        for (int ks = 0; ks < 4; ks++) {
            uint32_t pa[4], vb[16][2];
            LDSM_X4(pa[0], pa[1], pa[2], pa[3], sP + offPA + ks * 32);
            #pragma unroll
            for (int np = 0; np < 8; np++)
                LDSM_X4(vb[2*np][0], vb[2*np][1], vb[2*np+1][0], vb[2*np+1][1],
                        sV + offVB[np] + ks * 32);
            #pragma unroll
            for (int nt = 0; nt < 16; nt++)
                mma_f16(o[nt], pa, vb[nt]);
        }

        __syncthreads();   // all warps done reading Vts
        if (kt + 1 < nkt) {
            #pragma unroll
            for (int t = 0; t < 4; t++) {
                int idx = tid + t * 256;
                int r = idx >> 4;
                int dbase = (idx & 15) * 8;
                const __half* hh = (const __half*)&vreg[t];
                #pragma unroll
                for (int i = 0; i < 8; i++) Vts[(dbase + i) * VP + r] = hh[i];
            }
            CP_WAIT0();    // next K landed (issued a full iteration ago)
        }
        __syncthreads();
        cur ^= 1;
    }

    // --- normalize and write fp16 (feeds O-proj GEMM) ---
    const float inv0 = 1.0f / l0;
    const float inv1 = 1.0f / l1;
    const size_t row0 = (size_t)(b * S_LEN + q0 + wm0 + g);
    #pragma unroll
    for (int nt = 0; nt < 16; nt++) {
        const int col = h * HD + nt * 8 + 2 * t4;
        *(half2*)(out + row0 * H_DIM + col) =
            __floats2half2_rn(o[nt][0] * inv0, o[nt][1] * inv0);
        *(half2*)(out + (row0 + 8) * H_DIM + col) =
            __floats2half2_rn(o[nt][2] * inv1, o[nt][3] * inv1);
    }
}

// ---------------------------------------------------------------------------
// Launch
// ---------------------------------------------------------------------------
extern "C" void kernel_launch(void* const* d_in, const int* in_sizes, int n_in,
                              void* d_out, int out_size)
{
    const float* hidden = (const float*)d_in[0];
    const float* q_w    = (const float*)d_in[2];
    const float* k_w    = (const float*)d_in[3];
    const float* v_w    = (const float*)d_in[4];
    const float* o_w    = (const float*)d_in[5];
    const float* gate_w = (const float*)d_in[6];
    const float* up_w   = (const float*)d_in[7];
    const float* down_w = (const float*)d_in[8];
    const float* ln1    = (const float*)d_in[9];
    const float* ln2    = (const float*)d_in[10];
    float* out = (float*)d_out;

    __half *xn, *qkv, *attn, *gate, *ff, *wqkv, *wo, *wg, *wu, *wd;
    float *hbuf;
    cudaGetSymbolAddress((void**)&xn,   g_xn);
    cudaGetSymbolAddress((void**)&qkv,  g_qkv);
    cudaGetSymbolAddress((void**)&attn, g_attn);
    cudaGetSymbolAddress((void**)&hbuf, g_h);
    cudaGetSymbolAddress((void**)&gate, g_gate);
    cudaGetSymbolAddress((void**)&ff,   g_ff);
    cudaGetSymbolAddress((void**)&wqkv, g_wqkv);
    cudaGetSymbolAddress((void**)&wo,   g_wo);
    cudaGetSymbolAddress((void**)&wg,   g_wg);
    cudaGetSymbolAddress((void**)&wu,   g_wu);
    cudaGetSymbolAddress((void**)&wd,   g_wd);

    cudaFuncSetAttribute(flash_h, cudaFuncAttributeMaxDynamicSharedMemorySize, FLASH_SMEM);
    cudaFuncSetAttribute(gemm_h,  cudaFuncAttributeMaxDynamicSharedMemorySize, GEMM_SMEM);

    // 0) convert weights to fp16 (q|k|v concatenated); grid-stride ILP
    {
        auto cvt = [](const float* src, __half* dst, size_t n) {
            int n4 = (int)(n / 4);
            int grid = (n4 + 1023) / 1024;       // 4 float4 per thread
            cvt_wh_k<<<grid, 256>>>((const float4*)src, dst, n4);
        };
        cvt(q_w,    wqkv,                       (size_t)2048 * 2048);
        cvt(k_w,    wqkv + (size_t)2048 * 2048, (size_t)1024 * 2048);
        cvt(v_w,    wqkv + (size_t)3072 * 2048, (size_t)1024 * 2048);
        cvt(o_w,    wo, (size_t)2048 * 2048);
        cvt(gate_w, wg, (size_t)FF_DIM * 2048);
        cvt(up_w,   wu, (size_t)FF_DIM * 2048);
        cvt(down_w, wd, (size_t)2048 * FF_DIM);
    }

    // 1) rmsnorm(hidden) -> xn (fp16)
    rmsnorm_k<<<MROWS, 256>>>(hidden, ln1, xn);

    // 2) fused QKV projection -> qkv (fp16, q pre-scaled)
    gemm_h<<<dim3(32, 32), 256, GEMM_SMEM>>>(xn, H_DIM, wqkv, H_DIM, nullptr,
                                             qkv, QKV_LD, H_DIM, 3);

    // 3) fp16 tensor-core causal flash attention -> attn (2 CTAs/SM)
    flash_h<<<dim3(S_LEN / 128, NHEADS, B_SZ), 256, FLASH_SMEM>>>(qkv, attn);

    // 4) O projection + residual -> hbuf (fp32)
    gemm_h<<<dim3(16, 32), 256, GEMM_SMEM>>>(attn, H_DIM, wo, H_DIM, hidden,
                                             hbuf, H_DIM, H_DIM, 1);

    // 5) rmsnorm(hbuf) -> xn (fp16)
    rmsnorm_k<<<MROWS, 256>>>(hbuf, ln2, xn);

    // 6) gate projection -> gate (fp16 raw)
    gemm_h<<<dim3(44, 32), 256, GEMM_SMEM>>>(xn, H_DIM, wg, H_DIM, nullptr,
                                             gate, FF_DIM, H_DIM, 0);

    // 7) up projection + fused SwiGLU -> ff = h(silu(gate)*up) (fp16)
    gemm_h<<<dim3(44, 32), 256, GEMM_SMEM>>>(xn, H_DIM, wu, H_DIM, gate,
                                             ff, FF_DIM, H_DIM, 2);

    // 8) down projection + residual -> out (fp32)
    gemm_h<<<dim3(16, 32), 256, GEMM_SMEM>>>(ff, FF_DIM, wd, FF_DIM, hbuf,
                                             out, H_DIM, FF_DIM, 1);
}

// round 15
// speedup vs baseline: 1.0289x; 1.0286x over previous
#include <cuda_runtime.h>
#include <cuda_fp16.h>
#include <cstdint>
#include <cstddef>

// Problem constants
#define H_DIM   2048
#define S_LEN   2048
#define B_SZ    2
#define NHEADS  16
#define NKVH    8
#define HD      128
#define FF_DIM  5632
#define MROWS   (B_SZ * S_LEN)          // 4096
#define QKV_LD  4096                    // q(2048) | k(1024) | v(1024)
#define ATT_SCALE 0.08838834764831845f  // 1/sqrt(128)

// ---------------------------------------------------------------------------
// Scratch (activations fp16; residual stream fp32)
// ---------------------------------------------------------------------------
__device__ __half g_xn  [(size_t)MROWS * H_DIM];
__device__ __half g_qkv [(size_t)MROWS * QKV_LD];
__device__ __half g_attn[(size_t)MROWS * H_DIM];
__device__ float  g_h   [(size_t)MROWS * H_DIM];
__device__ __half g_gate[(size_t)MROWS * FF_DIM];
__device__ __half g_ff  [(size_t)MROWS * FF_DIM];
// fp16 weight copies
__device__ __half g_wqkv[(size_t)4096 * 2048];
__device__ __half g_wo[(size_t)2048 * 2048];
__device__ __half g_wg[(size_t)FF_DIM * 2048];
__device__ __half g_wu[(size_t)FF_DIM * 2048];
__device__ __half g_wd[(size_t)2048 * FF_DIM];

// ---------------------------------------------------------------------------
// Helpers (family-portable PTX: cp.async + mma.sync + ldmatrix)
// ---------------------------------------------------------------------------
__device__ __forceinline__ uint32_t smem_u32(const void* p) {
    uint32_t a;
    asm("{ .reg .u64 t; cvta.to.shared.u64 t, %1; cvt.u32.u64 %0, t; }"
        : "=r"(a) : "l"(p));
    return a;
}

__device__ __forceinline__ void cp_async16(uint32_t dst, const void* src) {
    asm volatile("cp.async.cg.shared.global [%0], [%1], 16;"
                 :: "r"(dst), "l"(src) : "memory");
}
#define CP_COMMIT() asm volatile("cp.async.commit_group;" ::: "memory")
#define CP_WAIT0()  asm volatile("cp.async.wait_group 0;" ::: "memory")

#define LDSM_X4(r0, r1, r2, r3, addr)                                        \
    asm volatile("ldmatrix.sync.aligned.m8n8.x4.shared.b16 {%0,%1,%2,%3}, [%4];" \
        : "=r"(r0), "=r"(r1), "=r"(r2), "=r"(r3) : "r"(addr))

// m16n8k16 fp16 MMA, fp32 accumulate (sm_80+ family-portable)
__device__ __forceinline__ void mma_f16(float* d, const uint32_t* a, const uint32_t* b) {
    asm volatile(
        "mma.sync.aligned.m16n8k16.row.col.f32.f16.f16.f32 "
        "{%0,%1,%2,%3}, {%4,%5,%6,%7}, {%8,%9}, {%0,%1,%2,%3};"
        : "+f"(d[0]), "+f"(d[1]), "+f"(d[2]), "+f"(d[3])
        : "r"(a[0]), "r"(a[1]), "r"(a[2]), "r"(a[3]), "r"(b[0]), "r"(b[1]));
}

__device__ __forceinline__ float silu_f(float x) {
    return x / (1.0f + __expf(-x));
}

// ---------------------------------------------------------------------------
// Weight convert: float -> fp16 (grid-stride)
// ---------------------------------------------------------------------------
__global__ __launch_bounds__(256) void cvt_wh_k(
    const float4* __restrict__ in, __half* __restrict__ out, int n4)
{
    const int stride = gridDim.x * 256;
    for (int i = blockIdx.x * 256 + threadIdx.x; i < n4; i += stride) {
        float4 v = in[i];
        half2* o = (half2*)(out + (size_t)i * 4);
        o[0] = __floats2half2_rn(v.x, v.y);
        o[1] = __floats2half2_rn(v.z, v.w);
    }
}

// ---------------------------------------------------------------------------
// fp16 tensor-core NT GEMM: C[m,n] = sum_k A[m,k]*B[n,k], epilogue modes:
//  0: half  C = h(acc)                   (raw half; used for gate)
//  1: float C = acc + Res(float)
//  2: half  C = h( silu(Res:half) * acc ) (fused SwiGLU; Res = gate fp16)
//  3: half  C = h( acc * (n0<2048 ? ATT_SCALE : 1) )  (fused QKV post)
// BM=BN=128, BK=64 halves, 8 warps (2x4), warp tile 64x32.
// 2-stage cp.async double buffer; single barrier per chunk (the trailing
// barrier is redundant: next iteration's wait+barrier precede any overwrite).
// Smem rows padded to 72 halves (144B = 9x16B, conflict-free ldmatrix).
// ---------------------------------------------------------------------------
#define HTILE_B (128 * 144)              // 18432 bytes per operand tile
#define HSTAGE_B (2 * HTILE_B)           // 36864 per stage (A+B)
#define GEMM_SMEM (2 * HSTAGE_B)         // 73728

__global__ __launch_bounds__(256, 2) void gemm_h(
    const __half* __restrict__ A, int lda,
    const __half* __restrict__ B, int ldb,
    const void* __restrict__ Resv,
    void* __restrict__ Cv, int ldc, int K, int mode)
{
    extern __shared__ __align__(1024) char sm[];
    const uint32_t sbase = smem_u32(sm);
    const int tid  = threadIdx.x;
    const int wid  = tid >> 5, lane = tid & 31;
    const int g    = lane >> 2, t4 = lane & 3;
    const int wm0  = (wid >> 2) * 64;
    const int wn0  = (wid & 3) * 32;
    const int m0   = blockIdx.y * 128;
    const int n0   = blockIdx.x * 128;

    const int j   = lane & 7;
    const int sel = lane >> 3;
    uint32_t offA[4], offB[2];
    #pragma unroll
    for (int mi = 0; mi < 4; mi++)
        offA[mi] = (uint32_t)((wm0 + mi * 16 + (sel & 1) * 8 + j) * 144 + (sel >> 1) * 16);
    #pragma unroll
    for (int np = 0; np < 2; np++)
        offB[np] = (uint32_t)((wn0 + np * 16 + (sel >> 1) * 8 + j) * 144 + (sel & 1) * 16);

    // cp.async map: 128 rows x 8 segs(16B) per operand; 2 threads/row, 4 segs each
    const int r0 = tid >> 1;
    const int sg = (tid & 1) * 4;
    const __half* Ab = A + (size_t)(m0 + r0) * lda + sg * 8;
    const __half* Bb = B + (size_t)(n0 + r0) * ldb + sg * 8;
    const uint32_t soff = (uint32_t)(r0 * 144 + sg * 16);

    float acc[4][4][4];
    #pragma unroll
    for (int mi = 0; mi < 4; mi++)
        #pragma unroll
        for (int ni = 0; ni < 4; ni++)
            #pragma unroll
            for (int jj = 0; jj < 4; jj++) acc[mi][ni][jj] = 0.0f;

    const int NC = K / 64;

    {
        const uint32_t sA = sbase + soff;
        const uint32_t sB = sA + HTILE_B;
        #pragma unroll
        for (int t = 0; t < 4; t++) {
            cp_async16(sA + t * 16, Ab + t * 8);
            cp_async16(sB + t * 16, Bb + t * 8);
        }
        CP_COMMIT();
    }

    for (int c = 0; c < NC; c++) {
        CP_WAIT0();
        __syncthreads();   // single barrier per chunk: all prior-stage reads done

        if (c + 1 < NC) {
            const uint32_t sA = sbase + ((c + 1) & 1) * HSTAGE_B + soff;
            const uint32_t sB = sA + HTILE_B;
            const __half* An = Ab + (size_t)(c + 1) * 64;
            const __half* Bn = Bb + (size_t)(c + 1) * 64;
            #pragma unroll
            for (int t = 0; t < 4; t++) {
                cp_async16(sA + t * 16, An + t * 8);
                cp_async16(sB + t * 16, Bn + t * 8);
            }
            CP_COMMIT();
        }

        const uint32_t stA = sbase + (c & 1) * HSTAGE_B;
        const uint32_t stB = stA + HTILE_B;

        #pragma unroll
        for (int ks = 0; ks < 4; ks++) {      // 4 k-steps of k16
            uint32_t ua[4][4], ub[4][2];
            #pragma unroll
            for (int mi = 0; mi < 4; mi++)
                LDSM_X4(ua[mi][0], ua[mi][1], ua[mi][2], ua[mi][3],
                        stA + offA[mi] + ks * 32);
            #pragma unroll
            for (int np = 0; np < 2; np++)
                LDSM_X4(ub[2*np][0], ub[2*np][1], ub[2*np+1][0], ub[2*np+1][1],
                        stB + offB[np] + ks * 32);
            #pragma unroll
            for (int mi = 0; mi < 4; mi++)
                #pragma unroll
                for (int ni = 0; ni < 4; ni++)
                    mma_f16(acc[mi][ni], ua[mi], ub[ni]);
        }
        // no trailing barrier: next iteration's CP_WAIT0+__syncthreads precede
        // any cp.async that could overwrite the stage just read.
    }

    const float qscale = (mode == 3 && n0 < 2048) ? ATT_SCALE : 1.0f;
    float* Cf = (float*)Cv;
    __half* Ch = (__half*)Cv;
    const float*  Rf = (const float*)Resv;
    const __half* Rh = (const __half*)Resv;

    #pragma unroll
    for (int mi = 0; mi < 4; mi++) {
        #pragma unroll
        for (int ni = 0; ni < 4; ni++) {
            const int row = m0 + wm0 + mi * 16 + g;
            const int col = n0 + wn0 + ni * 8 + 2 * t4;
            float2 v0 = make_float2(acc[mi][ni][0], acc[mi][ni][1]);
            float2 v1 = make_float2(acc[mi][ni][2], acc[mi][ni][3]);
            if (mode == 0) {
                *(half2*)(Ch + (size_t)row * ldc + col)       = __floats2half2_rn(v0.x, v0.y);
                *(half2*)(Ch + (size_t)(row + 8) * ldc + col) = __floats2half2_rn(v1.x, v1.y);
            } else if (mode == 1) {
                float2 e0 = *(const float2*)(Rf + (size_t)row * ldc + col);
                float2 e1 = *(const float2*)(Rf + (size_t)(row + 8) * ldc + col);
                v0.x += e0.x; v0.y += e0.y;
                v1.x += e1.x; v1.y += e1.y;
                *(float2*)(Cf + (size_t)row * ldc + col)       = v0;
                *(float2*)(Cf + (size_t)(row + 8) * ldc + col) = v1;
            } else if (mode == 2) {
                half2 h0 = *(const half2*)(Rh + (size_t)row * ldc + col);
                half2 h1 = *(const half2*)(Rh + (size_t)(row + 8) * ldc + col);
                float2 e0 = __half22float2(h0);
                float2 e1 = __half22float2(h1);
                *(half2*)(Ch + (size_t)row * ldc + col) =
                    __floats2half2_rn(silu_f(e0.x) * v0.x, silu_f(e0.y) * v0.y);
                *(half2*)(Ch + (size_t)(row + 8) * ldc + col) =
                    __floats2half2_rn(silu_f(e1.x) * v1.x, silu_f(e1.y) * v1.y);
            } else {
                *(half2*)(Ch + (size_t)row * ldc + col) =
                    __floats2half2_rn(v0.x * qscale, v0.y * qscale);
                *(half2*)(Ch + (size_t)(row + 8) * ldc + col) =
                    __floats2half2_rn(v1.x * qscale, v1.y * qscale);
            }
        }
    }
}

// ---------------------------------------------------------------------------
// RMSNorm: float in -> fp16 out
// ---------------------------------------------------------------------------
__global__ __launch_bounds__(256) void rmsnorm_k(
    const float* __restrict__ x, const float* __restrict__ w, __half* __restrict__ y)
{
    const int row = blockIdx.x;
    const float4* xr = (const float4*)(x + (size_t)row * H_DIM);
    half2* yr = (half2*)(y + (size_t)row * H_DIM);
    const float4* w4 = (const float4*)w;
    const int tid = threadIdx.x;

    float4 v0 = xr[tid];
    float4 v1 = xr[tid + 256];
    float s = v0.x*v0.x + v0.y*v0.y + v0.z*v0.z + v0.w*v0.w
            + v1.x*v1.x + v1.y*v1.y + v1.z*v1.z + v1.w*v1.w;

    #pragma unroll
    for (int off = 16; off; off >>= 1) s += __shfl_xor_sync(0xffffffffu, s, off);

    __shared__ float red[8];
    if ((tid & 31) == 0) red[tid >> 5] = s;
    __syncthreads();
    float tot = red[0] + red[1] + red[2] + red[3] + red[4] + red[5] + red[6] + red[7];
    const float inv = rsqrtf(tot * (1.0f / H_DIM) + 1e-6f);

    float4 w0 = w4[tid], w1 = w4[tid + 256];
    yr[2*tid]           = __floats2half2_rn(v0.x * inv * w0.x, v0.y * inv * w0.y);
    yr[2*tid + 1]       = __floats2half2_rn(v0.z * inv * w0.z, v0.w * inv * w0.w);
    yr[2*(tid+256)]     = __floats2half2_rn(v1.x * inv * w1.x, v1.y * inv * w1.y);
    yr[2*(tid+256) + 1] = __floats2half2_rn(v1.z * inv * w1.z, v1.w * inv * w1.w);
}

// ---------------------------------------------------------------------------
// fp16 tensor-core causal flash attention, GQA kvh = h>>1.
// (R12-proven config: 1 CTA/SM, no register cap -> no spills.)
// ---------------------------------------------------------------------------
#define QP 136    // halves per Q/K row (272B = 17*16B)
#define VP 72     // halves per Vt/P row (144B = 9*16B)
#define FLASH_SMEM ((128*QP + 2*64*QP + 128*VP + 128*VP) * 2)   // 106496

__global__ __launch_bounds__(256, 1) void flash_h(
    const __half* __restrict__ qkv, __half* __restrict__ out)
{
    extern __shared__ __half smh[];
    __half* Qs  = smh;                   // [128][136]
    __half* Ks  = Qs + 128 * QP;         // [2][64][136]
    __half* Vts = Ks + 2 * 64 * QP;      // [128][72]  d-major (transposed V)
    __half* Ps  = Vts + 128 * VP;        // [128][72]

    const int qt = gridDim.x - 1 - blockIdx.x;
    const int h  = blockIdx.y;
    const int b  = blockIdx.z;
    const int kvh = h >> 1;
    const int q0 = qt * 128;
    const int tid = threadIdx.x;
    const int wid = tid >> 5, lane = tid & 31;
    const int g = lane >> 2, t4 = lane & 3;
    const int j = lane & 7, sel = lane >> 3;
    const int wm0 = wid * 16;

    const __half* qbase = qkv + ((size_t)(b * S_LEN + q0)) * QKV_LD + h * HD;
    const __half* kbase = qkv + ((size_t)(b * S_LEN)) * QKV_LD + 2048 + kvh * HD;
    const __half* vbase = kbase + 1024;

    // Load Q tile (128 rows x 16 segs of 16B)
    #pragma unroll
    for (int t = 0; t < 8; t++) {
        int idx = tid + t * 256;
        int r = idx >> 4;
        int seg = idx & 15;
        *(uint4*)&Qs[r * QP + seg * 8] = *(const uint4*)(qbase + (size_t)r * QKV_LD + seg * 8);
    }

    const uint32_t sQ = smem_u32(Qs), sKb = smem_u32(Ks);
    const uint32_t sV = smem_u32(Vts), sP = smem_u32(Ps);

    // K cp.async map: 64 rows x 16 segs(16B); 4 threads/row, 4 segs each
    const int kr  = tid >> 2;
    const int ksg = (tid & 3) * 4;

    // ldmatrix lane byte-offsets
    const uint32_t offQA = (uint32_t)((wm0 + (sel & 1) * 8 + j) * (QP * 2) + (sel >> 1) * 16);
    uint32_t offKB[4];
    #pragma unroll
    for (int np = 0; np < 4; np++)
        offKB[np] = (uint32_t)((np * 16 + (sel >> 1) * 8 + j) * (QP * 2) + (sel & 1) * 16);
    const uint32_t offPA = (uint32_t)((wm0 + (sel & 1) * 8 + j) * (VP * 2) + (sel >> 1) * 16);
    uint32_t offVB[8];
    #pragma unroll
    for (int np = 0; np < 8; np++)
        offVB[np] = (uint32_t)((np * 16 + (sel >> 1) * 8 + j) * (VP * 2) + (sel & 1) * 16);

    float m0 = -1e30f, m1 = -1e30f, l0 = 0.0f, l1 = 0.0f;
    float o[16][4];
    #pragma unroll
    for (int nt = 0; nt < 16; nt++)
        #pragma unroll
        for (int c = 0; c < 4; c++) o[nt][c] = 0.0f;

    const int nkt = 2 * qt + 2;
    uint4 vreg[4];

    // ---- prologue: K0 via cp.async (full 16 segs/row), V0 via registers ----
    {
        const uint32_t dK = sKb + (uint32_t)(kr * (QP * 2));
        const __half* srcK = kbase + (size_t)kr * QKV_LD;
        #pragma unroll
        for (int t = 0; t < 4; t++)
            cp_async16(dK + (ksg + t) * 16, srcK + (ksg + t) * 8);
        CP_COMMIT();
        #pragma unroll
        for (int t = 0; t < 4; t++) {
            int idx = tid + t * 256;
            int r = idx >> 4;
            int seg = idx & 15;
            vreg[t] = *(const uint4*)(vbase + (size_t)r * QKV_LD + seg * 8);
        }
        CP_WAIT0();
        __syncthreads();
        #pragma unroll
        for (int t = 0; t < 4; t++) {
            int idx = tid + t * 256;
            int r = idx >> 4;
            int dbase = (idx & 15) * 8;
            const __half* hh = (const __half*)&vreg[t];
            #pragma unroll
            for (int i = 0; i < 8; i++) Vts[(dbase + i) * VP + r] = hh[i];
        }
        __syncthreads();
    }

    int cur = 0;
    for (int kt = 0; kt < nkt; kt++) {
        if (kt + 1 < nkt) {
            const int k1 = (kt + 1) * 64;
            const uint32_t dK = sKb + (uint32_t)((1 - cur) * 64 * QP * 2 + kr * (QP * 2));
            const __half* srcK = kbase + (size_t)(k1 + kr) * QKV_LD;
            #pragma unroll
            for (int t = 0; t < 4; t++)
                cp_async16(dK + (ksg + t) * 16, srcK + (ksg + t) * 8);
            CP_COMMIT();
            #pragma unroll
            for (int t = 0; t < 4; t++) {
                int idx = tid + t * 256;
                int r = idx >> 4;
                int seg = idx & 15;
                vreg[t] = *(const uint4*)(vbase + (size_t)(k1 + r) * QKV_LD + seg * 8);
            }
        }

        const int k0 = kt * 64;
        const uint32_t sK = sKb + (uint32_t)(cur * 64 * QP * 2);

        // --- S = Q K^T (16 q-rows x 64 k-cols per warp), HD/16 = 8 k-steps ---
        float s[8][4];
        #pragma unroll
        for (int nt = 0; nt < 8; nt++)
            #pragma unroll
            for (int c = 0; c < 4; c++) s[nt][c] = 0.0f;

        #pragma unroll
        for (int ks = 0; ks < 8; ks++) {
            uint32_t a[4], bb[8][2];
            LDSM_X4(a[0], a[1], a[2], a[3], sQ + offQA + ks * 32);
            #pragma unroll
            for (int np = 0; np < 4; np++)
                LDSM_X4(bb[2*np][0], bb[2*np][1], bb[2*np+1][0], bb[2*np+1][1],
                        sK + offKB[np] + ks * 32);
            #pragma unroll
            for (int nt = 0; nt < 8; nt++)
                mma_f16(s[nt], a, bb[nt]);
        }

        // --- causal mask (last two k-tiles only) ---
        if (kt >= 2 * qt) {
            const int r0g = q0 + wm0 + g;
            const int r1g = r0g + 8;
            #pragma unroll
            for (int nt = 0; nt < 8; nt++) {
                const int c0 = k0 + nt * 8 + 2 * t4;
                const int c1 = c0 + 1;
                if (c0 > r0g) s[nt][0] = -1e30f;
                if (c1 > r0g) s[nt][1] = -1e30f;
                if (c0 > r1g) s[nt][2] = -1e30f;
                if (c1 > r1g) s[nt][3] = -1e30f;
            }
        }

        // --- online softmax ---
        float mx0 = -1e30f, mx1 = -1e30f;
        #pragma unroll
        for (int nt = 0; nt < 8; nt++) {
            mx0 = fmaxf(mx0, fmaxf(s[nt][0], s[nt][1]));
            mx1 = fmaxf(mx1, fmaxf(s[nt][2], s[nt][3]));
        }
        mx0 = fmaxf(mx0, __shfl_xor_sync(0xffffffffu, mx0, 1));
        mx0 = fmaxf(mx0, __shfl_xor_sync(0xffffffffu, mx0, 2));
        mx1 = fmaxf(mx1, __shfl_xor_sync(0xffffffffu, mx1, 1));
        mx1 = fmaxf(mx1, __shfl_xor_sync(0xffffffffu, mx1, 2));

        const float nm0 = fmaxf(m0, mx0);
        const float nm1 = fmaxf(m1, mx1);
        const float al0 = __expf(m0 - nm0);
        const float al1 = __expf(m1 - nm1);
        m0 = nm0; m1 = nm1;

        float rs0 = 0.0f, rs1 = 0.0f;
        const int prow0 = (wm0 + g) * VP + 2 * t4;
        const int prow1 = (wm0 + g + 8) * VP + 2 * t4;
        #pragma unroll
        for (int nt = 0; nt < 8; nt++) {
            float p0 = __expf(s[nt][0] - nm0);
            float p1 = __expf(s[nt][1] - nm0);
            float p2 = __expf(s[nt][2] - nm1);
            float p3 = __expf(s[nt][3] - nm1);
            rs0 += p0 + p1;
            rs1 += p2 + p3;
            *(half2*)&Ps[prow0 + nt * 8] = __floats2half2_rn(p0, p1);
            *(half2*)&Ps[prow1 + nt * 8] = __floats2half2_rn(p2, p3);
        }
        rs0 += __shfl_xor_sync(0xffffffffu, rs0, 1);
        rs0 += __shfl_xor_sync(0xffffffffu, rs0, 2);
        rs1 += __shfl_xor_sync(0xffffffffu, rs1, 1);
        rs1 += __shfl_xor_sync(0xffffffffu, rs1, 2);
        l0 = l0 * al0 + rs0;
        l1 = l1 * al1 + rs1;

        #pragma unroll
        for (int nt = 0; nt < 16; nt++) {
            o[nt][0] *= al0; o[nt][1] *= al0;
            o[nt][2] *= al1; o[nt][3] *= al1;
        }
        __syncwarp();   // Ps rows are warp-private: order stores before ldmatrix

        // --- O += P V (16 q-rows x 128 d-cols per warp), 64/16 = 4 k-steps ---
        #pragma unroll
        for (int ks = 0; ks < 4; ks++) {
            uint32_t pa[4], vb[16][2];
            LDSM_X4(pa[0], pa[1], pa[2], pa[3], sP + offPA + ks * 32);
            #pragma unroll
            for (int np = 0; np < 8; np++)
                LDSM_X4(vb[2*np][0], vb[2*np][1], vb[2*np+1][0], vb[2*np+1][1],
                        sV + offVB[np] + ks * 32);
            #pragma unroll
            for (int nt = 0; nt < 16; nt++)
                mma_f16(o[nt], pa, vb[nt]);
        }

        __syncthreads();   // all warps done reading Vts
        if (kt + 1 < nkt) {
            #pragma unroll
            for (int t = 0; t < 4; t++) {
                int idx = tid + t * 256;
                int r = idx >> 4;
                int dbase = (idx & 15) * 8;
                const __half* hh = (const __half*)&vreg[t];
                #pragma unroll
                for (int i = 0; i < 8; i++) Vts[(dbase + i) * VP + r] = hh[i];
            }
            CP_WAIT0();    // next K landed (issued a full iteration ago)
        }
        __syncthreads();
        cur ^= 1;
    }

    // --- normalize and write fp16 (feeds O-proj GEMM) ---
    const float inv0 = 1.0f / l0;
    const float inv1 = 1.0f / l1;
    const size_t row0 = (size_t)(b * S_LEN + q0 + wm0 + g);
    #pragma unroll
    for (int nt = 0; nt < 16; nt++) {
        const int col = h * HD + nt * 8 + 2 * t4;
        *(half2*)(out + row0 * H_DIM + col) =
            __floats2half2_rn(o[nt][0] * inv0, o[nt][1] * inv0);
        *(half2*)(out + (row0 + 8) * H_DIM + col) =
            __floats2half2_rn(o[nt][2] * inv1, o[nt][3] * inv1);
    }
}

// ---------------------------------------------------------------------------
// Launch
// ---------------------------------------------------------------------------
extern "C" void kernel_launch(void* const* d_in, const int* in_sizes, int n_in,
                              void* d_out, int out_size)
{
    const float* hidden = (const float*)d_in[0];
    const float* q_w    = (const float*)d_in[2];
    const float* k_w    = (const float*)d_in[3];
    const float* v_w    = (const float*)d_in[4];
    const float* o_w    = (const float*)d_in[5];
    const float* gate_w = (const float*)d_in[6];
    const float* up_w   = (const float*)d_in[7];
    const float* down_w = (const float*)d_in[8];
    const float* ln1    = (const float*)d_in[9];
    const float* ln2    = (const float*)d_in[10];
    float* out = (float*)d_out;

    __half *xn, *qkv, *attn, *gate, *ff, *wqkv, *wo, *wg, *wu, *wd;
    float *hbuf;
    cudaGetSymbolAddress((void**)&xn,   g_xn);
    cudaGetSymbolAddress((void**)&qkv,  g_qkv);
    cudaGetSymbolAddress((void**)&attn, g_attn);
    cudaGetSymbolAddress((void**)&hbuf, g_h);
    cudaGetSymbolAddress((void**)&gate, g_gate);
    cudaGetSymbolAddress((void**)&ff,   g_ff);
    cudaGetSymbolAddress((void**)&wqkv, g_wqkv);
    cudaGetSymbolAddress((void**)&wo,   g_wo);
    cudaGetSymbolAddress((void**)&wg,   g_wg);
    cudaGetSymbolAddress((void**)&wu,   g_wu);
    cudaGetSymbolAddress((void**)&wd,   g_wd);

    cudaFuncSetAttribute(flash_h, cudaFuncAttributeMaxDynamicSharedMemorySize, FLASH_SMEM);
    cudaFuncSetAttribute(gemm_h,  cudaFuncAttributeMaxDynamicSharedMemorySize, GEMM_SMEM);

    // 0) convert weights to fp16 (q|k|v concatenated); grid-stride ILP
    {
        auto cvt = [](const float* src, __half* dst, size_t n) {
            int n4 = (int)(n / 4);
            int grid = (n4 + 1023) / 1024;       // 4 float4 per thread
            cvt_wh_k<<<grid, 256>>>((const float4*)src, dst, n4);
        };
        cvt(q_w,    wqkv,                       (size_t)2048 * 2048);
        cvt(k_w,    wqkv + (size_t)2048 * 2048, (size_t)1024 * 2048);
        cvt(v_w,    wqkv + (size_t)3072 * 2048, (size_t)1024 * 2048);
        cvt(o_w,    wo, (size_t)2048 * 2048);
        cvt(gate_w, wg, (size_t)FF_DIM * 2048);
        cvt(up_w,   wu, (size_t)FF_DIM * 2048);
        cvt(down_w, wd, (size_t)2048 * FF_DIM);
    }

    // 1) rmsnorm(hidden) -> xn (fp16)
    rmsnorm_k<<<MROWS, 256>>>(hidden, ln1, xn);

    // 2) fused QKV projection -> qkv (fp16, q pre-scaled)
    gemm_h<<<dim3(32, 32), 256, GEMM_SMEM>>>(xn, H_DIM, wqkv, H_DIM, nullptr,
                                             qkv, QKV_LD, H_DIM, 3);

    // 3) fp16 tensor-core causal flash attention -> attn (1 CTA/SM, no spills)
    flash_h<<<dim3(S_LEN / 128, NHEADS, B_SZ), 256, FLASH_SMEM>>>(qkv, attn);

    // 4) O projection + residual -> hbuf (fp32)
    gemm_h<<<dim3(16, 32), 256, GEMM_SMEM>>>(attn, H_DIM, wo, H_DIM, hidden,
                                             hbuf, H_DIM, H_DIM, 1);

    // 5) rmsnorm(hbuf) -> xn (fp16)
    rmsnorm_k<<<MROWS, 256>>>(hbuf, ln2, xn);

    // 6) gate projection -> gate (fp16 raw)
    gemm_h<<<dim3(44, 32), 256, GEMM_SMEM>>>(xn, H_DIM, wg, H_DIM, nullptr,
                                             gate, FF_DIM, H_DIM, 0);

    // 7) up projection + fused SwiGLU -> ff = h(silu(gate)*up) (fp16)
    gemm_h<<<dim3(44, 32), 256, GEMM_SMEM>>>(xn, H_DIM, wu, H_DIM, gate,
                                             ff, FF_DIM, H_DIM, 2);

    // 8) down projection + residual -> out (fp32)
    gemm_h<<<dim3(16, 32), 256, GEMM_SMEM>>>(ff, FF_DIM, wd, FF_DIM, hbuf,
                                             out, H_DIM, FF_DIM, 1);
}